// round 2
// baseline (speedup 1.0000x reference)
#include <cuda_runtime.h>
#include <mma.h>

using namespace nvcuda;

// Problem constants
#define MEM_DIM 1024
#define N_CHILD 16384

// GEMM tiling
#define BM 128
#define BN 128
#define BK 32
#define LDT 40   // smem tile leading dim (32 + 8 pad)
#define LDF 72   // epilogue f-tile leading dim (64 + 8 pad)

// Scratch (no cudaMalloc allowed): gate vectors + partial reduction buffer
__device__ float g_iou[3 * MEM_DIM];     // [0:1024)=i, [1024:2048)=u, [2048:3072)=o
__device__ float g_partial[MEM_DIM];

// ---------------------------------------------------------------------------
// Kernel 1: three GEMVs (i, u, o) + zero g_partial.
// 3072 warp-tasks, one output element per warp.
// ---------------------------------------------------------------------------
__global__ void iou_kernel(const float* __restrict__ hs,
                           const float* __restrict__ W_ih, const float* __restrict__ b_ih,
                           const float* __restrict__ W_uh, const float* __restrict__ b_uh,
                           const float* __restrict__ W_oh, const float* __restrict__ b_oh) {
    const int gtid = blockIdx.x * blockDim.x + threadIdx.x;
    if (gtid < MEM_DIM) g_partial[gtid] = 0.0f;

    const int task = gtid >> 5;
    const int lane = gtid & 31;
    if (task >= 3 * MEM_DIM) return;
    const int mat = task >> 10;       // 0=i, 1=u, 2=o
    const int j   = task & 1023;

    const float* W = (mat == 0) ? W_ih : ((mat == 1) ? W_uh : W_oh);
    const float* b = (mat == 0) ? b_ih : ((mat == 1) ? b_uh : b_oh);

    const float4* Wr = reinterpret_cast<const float4*>(W + (size_t)j * MEM_DIM);
    const float4* hv = reinterpret_cast<const float4*>(hs);

    float sum = 0.0f;
    #pragma unroll 8
    for (int c = lane; c < MEM_DIM / 4; c += 32) {
        float4 w4 = Wr[c];
        float4 h4 = hv[c];
        sum += w4.x * h4.x + w4.y * h4.y + w4.z * h4.z + w4.w * h4.w;
    }
    #pragma unroll
    for (int off = 16; off; off >>= 1)
        sum += __shfl_down_sync(0xffffffffu, sum, off);

    if (lane == 0) {
        float v = sum + b[j];
        float r = (mat == 1) ? tanhf(v) : (1.0f / (1.0f + __expf(-v)));
        g_iou[mat * MEM_DIM + j] = r;
    }
}

// ---------------------------------------------------------------------------
// Kernel 2: fused f-gate GEMM + sigmoid + child_c multiply + row reduction.
//   f[m][j] = sigmoid(sum_k child_h[m][k] * W_fh[j][k] + b_fh[j])
//   g_partial[j] += sum_m f[m][j] * child_c[m][j]
// CTA tile 128x128, K staged through smem, tf32 wmma (m16n16k8) mainloop.
// 8 warps, each owns a 32x64 sub-tile (2x4 wmma fragments).
// ---------------------------------------------------------------------------
__global__ void __launch_bounds__(256)
fgate_kernel(const float* __restrict__ child_h,
             const float* __restrict__ child_c,
             const float* __restrict__ W_fh,
             const float* __restrict__ b_fh) {
    __shared__ float smem[2 * BM * LDT];   // 10240 floats = 40 KB
    float* As = smem;                      // 128 x 32 (+pad): child_h tile
    float* Bs = smem + BM * LDT;           // 128 x 32 (+pad): W_fh tile

    const int jb  = blockIdx.x * BN;       // output-column block
    const int m0  = blockIdx.y * BM;       // child-row block
    const int tid = threadIdx.x;
    const int warp = tid >> 5;
    const int wy = warp >> 1;              // 0..3 : M sub-block (32 rows)
    const int wx = warp & 1;               // 0..1 : N sub-block (64 cols)

    wmma::fragment<wmma::accumulator, 16, 16, 8, float> acc[2][4];
    #pragma unroll
    for (int i = 0; i < 2; i++)
        #pragma unroll
        for (int j = 0; j < 4; j++)
            wmma::fill_fragment(acc[i][j], 0.0f);

    for (int k0 = 0; k0 < MEM_DIM; k0 += BK) {
        // Stage A and B tiles: 1024 float4 each, 256 threads x 4.
        #pragma unroll
        for (int it = 0; it < 4; ++it) {
            int idx = tid + it * 256;
            int row = idx >> 3;
            int c4  = (idx & 7) << 2;
            float4 a = *reinterpret_cast<const float4*>(
                child_h + (size_t)(m0 + row) * MEM_DIM + k0 + c4);
            *reinterpret_cast<float4*>(As + row * LDT + c4) = a;
            float4 w = *reinterpret_cast<const float4*>(
                W_fh + (size_t)(jb + row) * MEM_DIM + k0 + c4);
            *reinterpret_cast<float4*>(Bs + row * LDT + c4) = w;
        }
        __syncthreads();

        #pragma unroll
        for (int ks = 0; ks < BK / 8; ++ks) {
            wmma::fragment<wmma::matrix_a, 16, 16, 8, wmma::precision::tf32, wmma::row_major> af[2];
            wmma::fragment<wmma::matrix_b, 16, 16, 8, wmma::precision::tf32, wmma::col_major> bf[4];
            #pragma unroll
            for (int i = 0; i < 2; i++) {
                wmma::load_matrix_sync(af[i], As + (wy * 32 + i * 16) * LDT + ks * 8, LDT);
                #pragma unroll
                for (int e = 0; e < af[i].num_elements; e++)
                    af[i].x[e] = wmma::__float_to_tf32(af[i].x[e]);
            }
            #pragma unroll
            for (int j = 0; j < 4; j++) {
                wmma::load_matrix_sync(bf[j], Bs + (wx * 64 + j * 16) * LDT + ks * 8, LDT);
                #pragma unroll
                for (int e = 0; e < bf[j].num_elements; e++)
                    bf[j].x[e] = wmma::__float_to_tf32(bf[j].x[e]);
            }
            #pragma unroll
            for (int i = 0; i < 2; i++)
                #pragma unroll
                for (int j = 0; j < 4; j++)
                    wmma::mma_sync(acc[i][j], af[i], bf[j], acc[i][j]);
        }
        __syncthreads();
    }

    // Epilogue: two 64-column halves. Spill fragments to smem, apply
    // bias+sigmoid, multiply by child_c, reduce over the 128 rows.
    float* Fs = smem;                      // 128 x LDF (9216 floats, reuse)
    const int tcol = tid & 63;             // 0..63
    const int trow = tid >> 6;             // 0..3

    #pragma unroll
    for (int hx = 0; hx < 2; ++hx) {
        if (wx == hx) {
            #pragma unroll
            for (int i = 0; i < 2; i++)
                #pragma unroll
                for (int j = 0; j < 4; j++)
                    wmma::store_matrix_sync(Fs + (wy * 32 + i * 16) * LDF + j * 16,
                                            acc[i][j], LDF, wmma::mem_row_major);
        }
        __syncthreads();

        const int gcol = jb + hx * 64 + tcol;
        const float bias = b_fh[gcol];
        float s = 0.0f;
        #pragma unroll 4
        for (int m = trow; m < BM; m += 4) {
            float pre = Fs[m * LDF + tcol] + bias;
            float f = 1.0f / (1.0f + __expf(-pre));
            s += f * child_c[(size_t)(m0 + m) * MEM_DIM + gcol];
        }
        atomicAdd(&g_partial[gcol], s);
        __syncthreads();
    }
}

// ---------------------------------------------------------------------------
// Kernel 3: final combine. out[0:1024)=c, out[1024:2048)=h.
// ---------------------------------------------------------------------------
__global__ void finish_kernel(float* __restrict__ out) {
    const int j = blockIdx.x * blockDim.x + threadIdx.x;
    if (j < MEM_DIM) {
        float c = g_iou[j] * g_iou[MEM_DIM + j] + g_partial[j];
        out[j] = c;
        out[MEM_DIM + j] = g_iou[2 * MEM_DIM + j] * tanhf(c);
    }
}

// ---------------------------------------------------------------------------
// Launch. Input order (metadata): child_c, child_h, child_h_sum,
// W_ih, b_ih, W_fh, b_fh, W_uh, b_uh, W_oh, b_oh.
// ---------------------------------------------------------------------------
extern "C" void kernel_launch(void* const* d_in, const int* in_sizes, int n_in,
                              void* d_out, int out_size) {
    const float* child_c = (const float*)d_in[0];
    const float* child_h = (const float*)d_in[1];
    const float* hs      = (const float*)d_in[2];
    const float* W_ih    = (const float*)d_in[3];
    const float* b_ih    = (const float*)d_in[4];
    const float* W_fh    = (const float*)d_in[5];
    const float* b_fh    = (const float*)d_in[6];
    const float* W_uh    = (const float*)d_in[7];
    const float* b_uh    = (const float*)d_in[8];
    const float* W_oh    = (const float*)d_in[9];
    const float* b_oh    = (const float*)d_in[10];
    float* out = (float*)d_out;

    // 3072 warp-tasks -> 384 blocks x 256 threads (also zeroes g_partial)
    iou_kernel<<<384, 256>>>(hs, W_ih, b_ih, W_uh, b_uh, W_oh, b_oh);

    // x = column block (fastest) so consecutive CTAs share the A tile in L2
    dim3 grid(MEM_DIM / BN, N_CHILD / BM);   // (8, 128)
    fgate_kernel<<<grid, 256>>>(child_h, child_c, W_fh, b_fh);

    finish_kernel<<<1, 1024>>>(out);
}

// round 6
// speedup vs baseline: 1.8730x; 1.8730x over previous
#include <cuda_runtime.h>
#include <cstdint>

#define MEM_DIM 1024
#define N_CHILD 16384

// GEMM tiling
#define BM 128
#define BN 128
#define KB 32                    // K per stage (floats) = 128 B per row
#define NSTAGES 4
#define STAGE_BYTES 32768        // A 128x128B (16 KB) + B 128x128B (16 KB)
#define NUM_K 32                 // MEM_DIM / KB

// ---------------- scratch (no cudaMalloc allowed) ----------------
__device__ float g_iou[3 * MEM_DIM];   // i, u, o
__device__ float g_partial[MEM_DIM];

// ---------------- helpers ----------------
__device__ __forceinline__ uint32_t smem_u32(const void* p) {
    uint32_t a;
    asm("{ .reg .u64 t; cvta.to.shared.u64 t, %1; cvt.u32.u64 %0, t; }" : "=r"(a) : "l"(p));
    return a;
}

__device__ __forceinline__ void cp16(uint32_t dst, const void* src) {
    asm volatile("cp.async.cg.shared.global [%0], [%1], 16;" :: "r"(dst), "l"(src));
}

__device__ __forceinline__ uint32_t f2tf(float v) {   // round-to-nearest tf32
    uint32_t t;
    asm("cvt.rna.tf32.f32 %0, %1;" : "=r"(t) : "f"(v));
    return t;
}

__device__ __forceinline__ void mma1688(float* d, const uint32_t* a, const uint32_t* b) {
    asm volatile(
        "mma.sync.aligned.m16n8k8.row.col.f32.tf32.tf32.f32 "
        "{%0,%1,%2,%3}, {%4,%5,%6,%7}, {%8,%9}, {%0,%1,%2,%3};"
        : "+f"(d[0]), "+f"(d[1]), "+f"(d[2]), "+f"(d[3])
        : "r"(a[0]), "r"(a[1]), "r"(a[2]), "r"(a[3]), "r"(b[0]), "r"(b[1]));
}

// ---------------------------------------------------------------------------
// Kernel 1: three GEMVs (i, u, o) + zero g_partial.  (~6.5us)
// ---------------------------------------------------------------------------
__global__ void iou_kernel(const float* __restrict__ hs,
                           const float* __restrict__ W_ih, const float* __restrict__ b_ih,
                           const float* __restrict__ W_uh, const float* __restrict__ b_uh,
                           const float* __restrict__ W_oh, const float* __restrict__ b_oh) {
    const int gtid = blockIdx.x * blockDim.x + threadIdx.x;
    if (gtid < MEM_DIM) g_partial[gtid] = 0.0f;

    const int task = gtid >> 5;
    const int lane = gtid & 31;
    if (task >= 3 * MEM_DIM) return;
    const int mat = task >> 10;
    const int j   = task & 1023;

    const float* W = (mat == 0) ? W_ih : ((mat == 1) ? W_uh : W_oh);
    const float* b = (mat == 0) ? b_ih : ((mat == 1) ? b_uh : b_oh);

    const float4* Wr = reinterpret_cast<const float4*>(W + (size_t)j * MEM_DIM);
    const float4* hv = reinterpret_cast<const float4*>(hs);

    float sum = 0.0f;
    #pragma unroll 8
    for (int c = lane; c < MEM_DIM / 4; c += 32) {
        float4 w4 = Wr[c];
        float4 h4 = hv[c];
        sum += w4.x * h4.x + w4.y * h4.y + w4.z * h4.z + w4.w * h4.w;
    }
    #pragma unroll
    for (int off = 16; off; off >>= 1)
        sum += __shfl_down_sync(0xffffffffu, sum, off);

    if (lane == 0) {
        float v = sum + b[j];
        float r = (mat == 1) ? tanhf(v) : (1.0f / (1.0f + __expf(-v)));
        g_iou[mat * MEM_DIM + j] = r;
    }
}

// ---------------------------------------------------------------------------
// Kernel 2: pipelined tf32 mma.sync fused fgate GEMM + sigmoid + child_c
// multiply + column reduction.
//   pre[m][j] = child_h[m] . W_fh[j];  f = sigmoid(pre + b_fh[j])
//   g_partial[j] += sum_m f * child_c[m][j]
// CTA 128x128, 8 warps (4x2), warp tile 32x64 (2 x 8 m16n8k8 frags).
// ---------------------------------------------------------------------------
__device__ __forceinline__ void load_stage(uint32_t sbase,
                                           const float* __restrict__ A,
                                           const float* __restrict__ B,
                                           int m0, int jb, int k0, int tid) {
    #pragma unroll
    for (int i = 0; i < 8; ++i) {
        const int t = tid + (i << 8);          // 0..2047
        const int row = (t >> 3) & 127;
        const int c = t & 7;                   // 16B chunk within 128B row
        const uint32_t dst = sbase + ((t < 1024) ? 0u : 16384u)
                           + row * 128 + ((c ^ (row & 7)) << 4);
        const float* src = (t < 1024)
            ? (A + (size_t)(m0 + row) * MEM_DIM + k0 + c * 4)
            : (B + (size_t)(jb + row) * MEM_DIM + k0 + c * 4);
        cp16(dst, src);
    }
}

__global__ void __launch_bounds__(256, 1)
fgate_mma(const float* __restrict__ child_h,
          const float* __restrict__ child_c,
          const float* __restrict__ W_fh,
          const float* __restrict__ b_fh) {
    extern __shared__ char dsm[];
    __shared__ float s_red[BN];

    const int tid = threadIdx.x;
    const int jb = blockIdx.x * BN;
    const int m0 = blockIdx.y * BM;
    const int warp = tid >> 5;
    const int lane = tid & 31;
    const int wm = warp >> 1;          // 0..3  (M)
    const int wn = warp & 1;           // 0..1  (N)
    const int rr = lane >> 2;          // 0..7
    const int kk = lane & 3;           // 0..3

    const uint32_t sbase = smem_u32(dsm);

    float acc[2][8][4];
    #pragma unroll
    for (int i = 0; i < 2; ++i)
        #pragma unroll
        for (int j = 0; j < 8; ++j)
            #pragma unroll
            for (int q = 0; q < 4; ++q) acc[i][j][q] = 0.0f;

    // prologue: stages 0..2
    #pragma unroll
    for (int s = 0; s < NSTAGES - 1; ++s) {
        load_stage(sbase + s * STAGE_BYTES, child_h, W_fh, m0, jb, s * KB, tid);
        asm volatile("cp.async.commit_group;" ::: "memory");
    }

    #pragma unroll 1
    for (int k = 0; k < NUM_K; ++k) {
        asm volatile("cp.async.wait_group 2;" ::: "memory");
        __syncthreads();

        // prefetch stage k+3 (buffer freed: all warps passed iteration k-1)
        if (k + NSTAGES - 1 < NUM_K) {
            load_stage(sbase + ((k + NSTAGES - 1) & (NSTAGES - 1)) * STAGE_BYTES,
                       child_h, W_fh, m0, jb, (k + NSTAGES - 1) * KB, tid);
        }
        asm volatile("cp.async.commit_group;" ::: "memory");

        const char* sA = dsm + (k & (NSTAGES - 1)) * STAGE_BYTES;
        const char* sB = sA + 16384;

        #pragma unroll
        for (int ks = 0; ks < KB / 8; ++ks) {
            uint32_t a[2][4];
            #pragma unroll
            for (int i = 0; i < 2; ++i) {
                const int r0 = wm * 32 + i * 16 + rr;
                const int c0 = ((2 * ks) ^ rr) << 4;
                const int c1 = ((2 * ks + 1) ^ rr) << 4;
                a[i][0] = f2tf(*(const float*)(sA + r0 * 128 + c0 + kk * 4));
                a[i][1] = f2tf(*(const float*)(sA + (r0 + 8) * 128 + c0 + kk * 4));
                a[i][2] = f2tf(*(const float*)(sA + r0 * 128 + c1 + kk * 4));
                a[i][3] = f2tf(*(const float*)(sA + (r0 + 8) * 128 + c1 + kk * 4));
            }
            uint32_t b[8][2];
            #pragma unroll
            for (int j = 0; j < 8; ++j) {
                const int n = wn * 64 + j * 8 + rr;
                const int c0 = ((2 * ks) ^ rr) << 4;
                const int c1 = ((2 * ks + 1) ^ rr) << 4;
                b[j][0] = f2tf(*(const float*)(sB + n * 128 + c0 + kk * 4));
                b[j][1] = f2tf(*(const float*)(sB + n * 128 + c1 + kk * 4));
            }
            #pragma unroll
            for (int i = 0; i < 2; ++i)
                #pragma unroll
                for (int j = 0; j < 8; ++j)
                    mma1688(acc[i][j], a[i], b[j]);
        }
        __syncthreads();
    }
    asm volatile("cp.async.wait_group 0;" ::: "memory");
    __syncthreads();

    // ---------------- epilogue ----------------
    // Spill accumulators to smem F[128][132] (reuses pipeline buffers).
    float* F = (float*)dsm;
    const int FS = BN + 4;
    #pragma unroll
    for (int i = 0; i < 2; ++i) {
        const int r0 = wm * 32 + i * 16 + rr;
        #pragma unroll
        for (int j = 0; j < 8; ++j) {
            const int c = wn * 64 + j * 8 + kk * 2;
            F[r0 * FS + c]           = acc[i][j][0];
            F[r0 * FS + c + 1]       = acc[i][j][1];
            F[(r0 + 8) * FS + c]     = acc[i][j][2];
            F[(r0 + 8) * FS + c + 1] = acc[i][j][3];
        }
    }
    __syncthreads();

    // 256 threads: 2 threads per column, 64 rows each.
    const int col  = tid & 127;
    const int half = tid >> 7;
    const float bias = __ldg(&b_fh[jb + col]);
    const float* crow = child_c + (size_t)(m0 + half * 64) * MEM_DIM + jb + col;

    float s = 0.0f;
    #pragma unroll 4
    for (int m = 0; m < 64; ++m) {
        const float pre = F[(half * 64 + m) * FS + col] + bias;
        const float f = 1.0f / (1.0f + __expf(-pre));
        s += f * crow[(size_t)m * MEM_DIM];
    }
    if (half == 1) s_red[col] = s;
    __syncthreads();
    if (half == 0) atomicAdd(&g_partial[jb + col], s + s_red[col]);
}

// ---------------------------------------------------------------------------
// Kernel 3: final combine. out[0:1024)=c, out[1024:2048)=h.
// ---------------------------------------------------------------------------
__global__ void finish_kernel(float* __restrict__ out) {
    const int j = blockIdx.x * blockDim.x + threadIdx.x;
    if (j < MEM_DIM) {
        float c = g_iou[j] * g_iou[MEM_DIM + j] + g_partial[j];
        out[j] = c;
        out[MEM_DIM + j] = g_iou[2 * MEM_DIM + j] * tanhf(c);
    }
}

// ---------------------------------------------------------------------------
// Launch. Input order: child_c, child_h, child_h_sum,
// W_ih, b_ih, W_fh, b_fh, W_uh, b_uh, W_oh, b_oh.
// ---------------------------------------------------------------------------
extern "C" void kernel_launch(void* const* d_in, const int* in_sizes, int n_in,
                              void* d_out, int out_size) {
    (void)in_sizes; (void)n_in; (void)out_size;
    const float* child_c = (const float*)d_in[0];
    const float* child_h = (const float*)d_in[1];
    const float* hs      = (const float*)d_in[2];
    const float* W_ih    = (const float*)d_in[3];
    const float* b_ih    = (const float*)d_in[4];
    const float* W_fh    = (const float*)d_in[5];
    const float* b_fh    = (const float*)d_in[6];
    const float* W_uh    = (const float*)d_in[7];
    const float* b_uh    = (const float*)d_in[8];
    const float* W_oh    = (const float*)d_in[9];
    const float* b_oh    = (const float*)d_in[10];
    float* out = (float*)d_out;

    const int dyn_smem = NSTAGES * STAGE_BYTES;   // 128 KB
    static int attr_set = 0;
    if (!attr_set) {
        cudaFuncSetAttribute(fgate_mma, cudaFuncAttributeMaxDynamicSharedMemorySize, dyn_smem);
        attr_set = 1;
    }

    iou_kernel<<<384, 256>>>(hs, W_ih, b_ih, W_uh, b_uh, W_oh, b_oh);

    dim3 grid(MEM_DIM / BN, N_CHILD / BM);   // (8, 128); x fastest for A reuse in L2
    fgate_mma<<<grid, 256, dyn_smem>>>(child_h, child_c, W_fh, b_fh);

    finish_kernel<<<1, 1024>>>(out);
}

// round 7
// speedup vs baseline: 2.4154x; 1.2896x over previous
#include <cuda_runtime.h>
#include <cuda_fp16.h>
#include <cstdint>

#define MEM_DIM 1024
#define N_CHILD 16384

// GEMM tiling (fp16 operands)
#define BM 128
#define BN 128
#define KB 64                    // K per stage (halves) = 128 B per row
#define NSTAGES 4
#define STAGE_BYTES 32768        // A 128x128B + B 128x128B
#define NUM_K 16                 // MEM_DIM / KB

// ---------------- scratch (no cudaMalloc allowed) ----------------
__device__ float  g_iou[3 * MEM_DIM];                 // i, u, o
__device__ float  g_partial[MEM_DIM];
__device__ __half g_Ah[(size_t)N_CHILD * MEM_DIM];    // fp16 child_h (32 MB)
__device__ __half g_Wf[(size_t)MEM_DIM * MEM_DIM];    // fp16 W_fh    (2 MB)

// ---------------- helpers ----------------
__device__ __forceinline__ uint32_t smem_u32(const void* p) {
    uint32_t a;
    asm("{ .reg .u64 t; cvta.to.shared.u64 t, %1; cvt.u32.u64 %0, t; }" : "=r"(a) : "l"(p));
    return a;
}

__device__ __forceinline__ void cp16(uint32_t dst, const void* src) {
    asm volatile("cp.async.cg.shared.global [%0], [%1], 16;" :: "r"(dst), "l"(src));
}

__device__ __forceinline__ void ldsm_x4(uint32_t* r, uint32_t addr) {
    asm volatile("ldmatrix.sync.aligned.m8n8.x4.shared.b16 {%0,%1,%2,%3}, [%4];"
                 : "=r"(r[0]), "=r"(r[1]), "=r"(r[2]), "=r"(r[3]) : "r"(addr));
}

__device__ __forceinline__ void mma16816(float* d, const uint32_t* a, const uint32_t* b) {
    asm volatile(
        "mma.sync.aligned.m16n8k16.row.col.f32.f16.f16.f32 "
        "{%0,%1,%2,%3}, {%4,%5,%6,%7}, {%8,%9}, {%0,%1,%2,%3};"
        : "+f"(d[0]), "+f"(d[1]), "+f"(d[2]), "+f"(d[3])
        : "r"(a[0]), "r"(a[1]), "r"(a[2]), "r"(a[3]), "r"(b[0]), "r"(b[1]));
}

// ---------------------------------------------------------------------------
// Kernel 0: convert child_h and W_fh to fp16 scratch.
// ---------------------------------------------------------------------------
__global__ void convert_inputs(const float* __restrict__ h, const float* __restrict__ w) {
    const int stride = gridDim.x * blockDim.x;
    const int i0 = blockIdx.x * blockDim.x + threadIdx.x;

    const float4* h4 = reinterpret_cast<const float4*>(h);
    uint2* a2 = reinterpret_cast<uint2*>(g_Ah);
    for (int t = i0; t < (N_CHILD * MEM_DIM) / 4; t += stride) {
        float4 v = h4[t];
        __half2 lo = __floats2half2_rn(v.x, v.y);
        __half2 hi = __floats2half2_rn(v.z, v.w);
        a2[t] = make_uint2(*reinterpret_cast<uint32_t*>(&lo),
                           *reinterpret_cast<uint32_t*>(&hi));
    }
    const float4* w4 = reinterpret_cast<const float4*>(w);
    uint2* b2 = reinterpret_cast<uint2*>(g_Wf);
    for (int t = i0; t < (MEM_DIM * MEM_DIM) / 4; t += stride) {
        float4 v = w4[t];
        __half2 lo = __floats2half2_rn(v.x, v.y);
        __half2 hi = __floats2half2_rn(v.z, v.w);
        b2[t] = make_uint2(*reinterpret_cast<uint32_t*>(&lo),
                           *reinterpret_cast<uint32_t*>(&hi));
    }
}

// ---------------------------------------------------------------------------
// Kernel 1: three GEMVs (i, u, o) + zero g_partial.  (~6.5us)
// ---------------------------------------------------------------------------
__global__ void iou_kernel(const float* __restrict__ hs,
                           const float* __restrict__ W_ih, const float* __restrict__ b_ih,
                           const float* __restrict__ W_uh, const float* __restrict__ b_uh,
                           const float* __restrict__ W_oh, const float* __restrict__ b_oh) {
    const int gtid = blockIdx.x * blockDim.x + threadIdx.x;
    if (gtid < MEM_DIM) g_partial[gtid] = 0.0f;

    const int task = gtid >> 5;
    const int lane = gtid & 31;
    if (task >= 3 * MEM_DIM) return;
    const int mat = task >> 10;
    const int j   = task & 1023;

    const float* W = (mat == 0) ? W_ih : ((mat == 1) ? W_uh : W_oh);
    const float* b = (mat == 0) ? b_ih : ((mat == 1) ? b_uh : b_oh);

    const float4* Wr = reinterpret_cast<const float4*>(W + (size_t)j * MEM_DIM);
    const float4* hv = reinterpret_cast<const float4*>(hs);

    float sum = 0.0f;
    #pragma unroll 8
    for (int c = lane; c < MEM_DIM / 4; c += 32) {
        float4 w4 = Wr[c];
        float4 h4 = hv[c];
        sum += w4.x * h4.x + w4.y * h4.y + w4.z * h4.z + w4.w * h4.w;
    }
    #pragma unroll
    for (int off = 16; off; off >>= 1)
        sum += __shfl_down_sync(0xffffffffu, sum, off);

    if (lane == 0) {
        float v = sum + b[j];
        float r = (mat == 1) ? tanhf(v) : (1.0f / (1.0f + __expf(-v)));
        g_iou[mat * MEM_DIM + j] = r;
    }
}

// ---------------------------------------------------------------------------
// Kernel 2: fp16 mma.sync fused fgate GEMM + sigmoid + child_c + reduction.
// CTA 128x128, 8 warps (4x2), warp tile 32x64, ldmatrix fragment loads.
// ---------------------------------------------------------------------------
__device__ __forceinline__ void load_stage(uint32_t sbase, int m0, int jb, int k0, int tid) {
    #pragma unroll
    for (int i = 0; i < 8; ++i) {
        const int t = tid + (i << 8);          // 0..2047 16B-chunks
        const int row = (t >> 3) & 127;
        const int c = t & 7;                   // 16B chunk within 128B row
        const uint32_t dst = sbase + ((t < 1024) ? 0u : 16384u)
                           + row * 128 + ((c ^ (row & 7)) << 4);
        const __half* src = (t < 1024)
            ? (g_Ah + (size_t)(m0 + row) * MEM_DIM + k0 + c * 8)
            : (g_Wf + (size_t)(jb + row) * MEM_DIM + k0 + c * 8);
        cp16(dst, src);
    }
}

__global__ void __launch_bounds__(256, 1)
fgate_mma(const float* __restrict__ child_c, const float* __restrict__ b_fh) {
    extern __shared__ char dsm[];
    __shared__ float s_red[BN];

    const int tid = threadIdx.x;
    const int jb = blockIdx.x * BN;
    const int m0 = blockIdx.y * BM;
    const int warp = tid >> 5;
    const int lane = tid & 31;
    const int wm = warp >> 1;          // 0..3  (M)
    const int wn = warp & 1;           // 0..1  (N)
    const int rr = lane >> 2;          // 0..7
    const int kk = lane & 3;           // 0..3
    const int g  = lane >> 3;          // ldmatrix lane group 0..3
    const int lr = lane & 7;

    const uint32_t sbase = smem_u32(dsm);

    float acc[2][8][4];
    #pragma unroll
    for (int i = 0; i < 2; ++i)
        #pragma unroll
        for (int j = 0; j < 8; ++j)
            #pragma unroll
            for (int q = 0; q < 4; ++q) acc[i][j][q] = 0.0f;

    // prologue
    #pragma unroll
    for (int s = 0; s < NSTAGES - 1; ++s) {
        load_stage(sbase + s * STAGE_BYTES, m0, jb, s * KB, tid);
        asm volatile("cp.async.commit_group;" ::: "memory");
    }

    // per-lane ldmatrix row/offset pre-computation
    // A frag i: rows wm*32 + i*16 + (g&1)*8 + lr ; chunk += (g>>1)
    // B frag pair j: rows wn*64 + j*16 + (g>>1)*8 + lr ; chunk += (g&1)
    const int arow0 = wm * 32 + (g & 1) * 8 + lr;
    const int brow0 = wn * 64 + (g >> 1) * 8 + lr;
    const int achunk_add = g >> 1;
    const int bchunk_add = g & 1;

    #pragma unroll 1
    for (int k = 0; k < NUM_K; ++k) {
        asm volatile("cp.async.wait_group 2;" ::: "memory");
        __syncthreads();

        if (k + NSTAGES - 1 < NUM_K) {
            load_stage(sbase + ((k + NSTAGES - 1) & (NSTAGES - 1)) * STAGE_BYTES,
                       m0, jb, (k + NSTAGES - 1) * KB, tid);
        }
        asm volatile("cp.async.commit_group;" ::: "memory");

        const uint32_t sA = sbase + (k & (NSTAGES - 1)) * STAGE_BYTES;
        const uint32_t sB = sA + 16384;

        #pragma unroll
        for (int ks = 0; ks < KB / 16; ++ks) {     // 4 k16 steps
            const int kc = 2 * ks;
            uint32_t a[2][4];
            #pragma unroll
            for (int i = 0; i < 2; ++i) {
                const int row = arow0 + i * 16;
                const int ch = (kc + achunk_add) ^ (row & 7);
                ldsm_x4(a[i], sA + row * 128 + (ch << 4));
            }
            uint32_t b[8][2];
            #pragma unroll
            for (int j = 0; j < 4; ++j) {
                const int row = brow0 + j * 16;
                const int ch = (kc + bchunk_add) ^ (row & 7);
                uint32_t r[4];
                ldsm_x4(r, sB + row * 128 + (ch << 4));
                b[2 * j][0] = r[0]; b[2 * j][1] = r[1];
                b[2 * j + 1][0] = r[2]; b[2 * j + 1][1] = r[3];
            }
            #pragma unroll
            for (int i = 0; i < 2; ++i)
                #pragma unroll
                for (int j = 0; j < 8; ++j)
                    mma16816(acc[i][j], a[i], b[j]);
        }
        __syncthreads();
    }
    asm volatile("cp.async.wait_group 0;" ::: "memory");
    __syncthreads();

    // ---------------- epilogue ----------------
    float* F = (float*)dsm;
    const int FS = BN + 4;
    #pragma unroll
    for (int i = 0; i < 2; ++i) {
        const int r0 = wm * 32 + i * 16 + rr;
        #pragma unroll
        for (int j = 0; j < 8; ++j) {
            const int c = wn * 64 + j * 8 + kk * 2;
            F[r0 * FS + c]           = acc[i][j][0];
            F[r0 * FS + c + 1]       = acc[i][j][1];
            F[(r0 + 8) * FS + c]     = acc[i][j][2];
            F[(r0 + 8) * FS + c + 1] = acc[i][j][3];
        }
    }
    __syncthreads();

    const int col  = tid & 127;
    const int half = tid >> 7;
    const float bias = __ldg(&b_fh[jb + col]);
    const float* crow = child_c + (size_t)(m0 + half * 64) * MEM_DIM + jb + col;

    float s = 0.0f;
    #pragma unroll 4
    for (int m = 0; m < 64; ++m) {
        const float pre = F[(half * 64 + m) * FS + col] + bias;
        const float f = 1.0f / (1.0f + __expf(-pre));
        s += f * crow[(size_t)m * MEM_DIM];
    }
    if (half == 1) s_red[col] = s;
    __syncthreads();
    if (half == 0) atomicAdd(&g_partial[jb + col], s + s_red[col]);
}

// ---------------------------------------------------------------------------
// Kernel 3: final combine. out[0:1024)=c, out[1024:2048)=h.
// ---------------------------------------------------------------------------
__global__ void finish_kernel(float* __restrict__ out) {
    const int j = blockIdx.x * blockDim.x + threadIdx.x;
    if (j < MEM_DIM) {
        float c = g_iou[j] * g_iou[MEM_DIM + j] + g_partial[j];
        out[j] = c;
        out[MEM_DIM + j] = g_iou[2 * MEM_DIM + j] * tanhf(c);
    }
}

// ---------------------------------------------------------------------------
// Launch. Input order: child_c, child_h, child_h_sum,
// W_ih, b_ih, W_fh, b_fh, W_uh, b_uh, W_oh, b_oh.
// ---------------------------------------------------------------------------
extern "C" void kernel_launch(void* const* d_in, const int* in_sizes, int n_in,
                              void* d_out, int out_size) {
    (void)in_sizes; (void)n_in; (void)out_size;
    const float* child_c = (const float*)d_in[0];
    const float* child_h = (const float*)d_in[1];
    const float* hs      = (const float*)d_in[2];
    const float* W_ih    = (const float*)d_in[3];
    const float* b_ih    = (const float*)d_in[4];
    const float* W_fh    = (const float*)d_in[5];
    const float* b_fh    = (const float*)d_in[6];
    const float* W_uh    = (const float*)d_in[7];
    const float* b_uh    = (const float*)d_in[8];
    const float* W_oh    = (const float*)d_in[9];
    const float* b_oh    = (const float*)d_in[10];
    float* out = (float*)d_out;

    const int dyn_smem = NSTAGES * STAGE_BYTES;   // 128 KB
    static int attr_set = 0;
    if (!attr_set) {
        cudaFuncSetAttribute(fgate_mma, cudaFuncAttributeMaxDynamicSharedMemorySize, dyn_smem);
        attr_set = 1;
    }

    convert_inputs<<<1024, 256>>>(child_h, W_fh);
    iou_kernel<<<384, 256>>>(hs, W_ih, b_ih, W_uh, b_uh, W_oh, b_oh);

    dim3 grid(MEM_DIM / BN, N_CHILD / BM);   // (8, 128); x fastest for A reuse in L2
    fgate_mma<<<grid, 256, dyn_smem>>>(child_c, b_fh);

    finish_kernel<<<1, 1024>>>(out);
}